// round 1
// baseline (speedup 1.0000x reference)
#include <cuda_runtime.h>
#include <cstdint>
#include <math.h>

// Problem dims (fixed by the dataset)
#define R_TOT 4096      // B*N
#define D_TOT 512
#define K_NB  32
#define H_NUM 4
#define DH    128

// Scratch (static device arrays: allocation-free per harness rules)
__device__ float g_q [R_TOT * D_TOT];            // 8 MB
__device__ float g_t [R_TOT * H_NUM * D_TOT];    // 33 MB
__device__ float g_eb[R_TOT * H_NUM * D_TOT];    // 33 MB

// ---- packed f32x2 helpers (Blackwell FFMA2 path) ----
__device__ __forceinline__ unsigned long long ffma2(unsigned long long a,
                                                    unsigned long long b,
                                                    unsigned long long c) {
    unsigned long long d;
    asm("fma.rn.f32x2 %0, %1, %2, %3;" : "=l"(d) : "l"(a), "l"(b), "l"(c));
    return d;
}
__device__ __forceinline__ unsigned long long pack2(float lo, float hi) {
    unsigned long long d;
    asm("mov.b64 %0, {%1, %2};" : "=l"(d) : "f"(lo), "f"(hi));
    return d;
}
__device__ __forceinline__ float2 unpack2(unsigned long long v) {
    float2 r;
    asm("mov.b64 {%0, %1}, %2;" : "=f"(r.x), "=f"(r.y) : "l"(v));
    return r;
}

// ============================================================================
// Tiled SGEMM: C[m,n] = sum_k A[m,k] * B(k,n) (+ bias[n])
//   BT=true : B stored [n][k] (k contiguous)   -> C = A @ B^T
//   BT=false: B stored [k][n] (n contiguous)   -> C = A @ B
// Tile 128x128x16, 256 threads, 8x8 per thread, f32x2 accumulate.
// Requires M%128==0, N%128==0, K%16==0 (true for all our shapes).
// blockIdx.z batches heads via aZ/bZ/cZ/biasZ element offsets.
// ============================================================================
template<bool BT, bool BIAS>
__global__ void __launch_bounds__(256) sgemm_k(
    const float* __restrict__ A, int lda, int aZ,
    const float* __restrict__ B, int ldb, int bZ,
    float*       __restrict__ C, int ldc, int cZ,
    const float* __restrict__ bias, int biasZ,
    int Kd)
{
    __shared__ float As[16][128];
    __shared__ float Bs[16][128];

    const int tid = threadIdx.x;
    const int bm = blockIdx.x * 128;
    const int bn = blockIdx.y * 128;
    A += (size_t)blockIdx.z * aZ;
    B += (size_t)blockIdx.z * bZ;
    C += (size_t)blockIdx.z * cZ;

    const int tr = tid >> 4;          // 0..15 (row group)
    const int tc = tid & 15;          // 0..15 (col group)

    // K-contiguous loader mapping (A, and B when BT): 2 threads per row, 8 floats each
    const int lrow = tid >> 1;        // 0..127
    const int lseg = (tid & 1) * 8;   // 0 or 8
    // N-contiguous loader mapping (B when !BT)
    const int bk = tid >> 4;          // 0..15
    const int bc = (tid & 15) * 8;    // 0..120

    unsigned long long acc[8][4];
    #pragma unroll
    for (int i = 0; i < 8; i++)
        #pragma unroll
        for (int j = 0; j < 4; j++) acc[i][j] = 0ull;   // bits of {0.f,0.f}

    for (int k0 = 0; k0 < Kd; k0 += 16) {
        // ---- load A tile (transpose into As[k][m]) ----
        {
            const float* ap = A + (size_t)(bm + lrow) * lda + k0 + lseg;
            float4 a0 = *(const float4*)(ap);
            float4 a1 = *(const float4*)(ap + 4);
            As[lseg+0][lrow] = a0.x; As[lseg+1][lrow] = a0.y;
            As[lseg+2][lrow] = a0.z; As[lseg+3][lrow] = a0.w;
            As[lseg+4][lrow] = a1.x; As[lseg+5][lrow] = a1.y;
            As[lseg+6][lrow] = a1.z; As[lseg+7][lrow] = a1.w;
        }
        // ---- load B tile ----
        if (BT) {
            const float* bp = B + (size_t)(bn + lrow) * ldb + k0 + lseg;
            float4 b0 = *(const float4*)(bp);
            float4 b1 = *(const float4*)(bp + 4);
            Bs[lseg+0][lrow] = b0.x; Bs[lseg+1][lrow] = b0.y;
            Bs[lseg+2][lrow] = b0.z; Bs[lseg+3][lrow] = b0.w;
            Bs[lseg+4][lrow] = b1.x; Bs[lseg+5][lrow] = b1.y;
            Bs[lseg+6][lrow] = b1.z; Bs[lseg+7][lrow] = b1.w;
        } else {
            const float* bp = B + (size_t)(k0 + bk) * ldb + bn + bc;
            float4 b0 = *(const float4*)(bp);
            float4 b1 = *(const float4*)(bp + 4);
            *(float4*)&Bs[bk][bc]     = b0;
            *(float4*)&Bs[bk][bc + 4] = b1;
        }
        __syncthreads();

        #pragma unroll
        for (int kk = 0; kk < 16; kk++) {
            float a[8], b[8];
            *(float4*)(a)     = *(const float4*)&As[kk][tr * 4];
            *(float4*)(a + 4) = *(const float4*)&As[kk][64 + tr * 4];
            *(float4*)(b)     = *(const float4*)&Bs[kk][tc * 4];
            *(float4*)(b + 4) = *(const float4*)&Bs[kk][64 + tc * 4];
            unsigned long long b2[4];
            b2[0] = pack2(b[0], b[1]); b2[1] = pack2(b[2], b[3]);
            b2[2] = pack2(b[4], b[5]); b2[3] = pack2(b[6], b[7]);
            #pragma unroll
            for (int i = 0; i < 8; i++) {
                unsigned long long a2 = pack2(a[i], a[i]);
                #pragma unroll
                for (int j = 0; j < 4; j++)
                    acc[i][j] = ffma2(a2, b2[j], acc[i][j]);
            }
        }
        __syncthreads();
    }

    // ---- epilogue ----
    float bb[8];
    if (BIAS) {
        const float* bp = bias + (size_t)blockIdx.z * biasZ + bn;
        #pragma unroll
        for (int j = 0; j < 4; j++) {
            bb[j]     = bp[tc * 4 + j];
            bb[4 + j] = bp[64 + tc * 4 + j];
        }
    } else {
        #pragma unroll
        for (int j = 0; j < 8; j++) bb[j] = 0.f;
    }
    #pragma unroll
    for (int i = 0; i < 8; i++) {
        int rl = (i < 4) ? (tr * 4 + i) : (64 + tr * 4 + (i - 4));
        float* Cp = C + (size_t)(bm + rl) * ldc + bn;
        float2 u0 = unpack2(acc[i][0]);
        float2 u1 = unpack2(acc[i][1]);
        float2 u2 = unpack2(acc[i][2]);
        float2 u3 = unpack2(acc[i][3]);
        float4 o0 = make_float4(u0.x + bb[0], u0.y + bb[1], u1.x + bb[2], u1.y + bb[3]);
        float4 o1 = make_float4(u2.x + bb[4], u2.y + bb[5], u3.x + bb[6], u3.y + bb[7]);
        *(float4*)(Cp + tc * 4)      = o0;
        *(float4*)(Cp + 64 + tc * 4) = o1;
    }
}

// ============================================================================
// Fused attention kernel: one CTA per (b,n) row.
//   scores[h][k] = t[h] . e[k]  (512-dot), mask -> -1e9, softmax over k,
//   eb[h][d] = sum_k attn[h][k] * e[k][d]
// smem: e tile [32][512] (64KB) + t [4][512] (8KB) + scores/attn
// ============================================================================
#define ATTN_SMEM (K_NB * D_TOT * 4 + H_NUM * D_TOT * 4 + H_NUM * K_NB * 4 * 2)

__global__ void __launch_bounds__(256) attn_k(
    const float* __restrict__ e,     // [R, 32, 512]
    const int*   __restrict__ mask,  // [R, 32]
    const float* __restrict__ t,     // [R, 4, 512]
    float*       __restrict__ eb)    // [R, 4, 512]
{
    extern __shared__ float sm[];
    float* se     = sm;                       // [32][512]
    float* st     = se + K_NB * D_TOT;        // [4][512]
    float* sscore = st + H_NUM * D_TOT;       // [4][32]
    float* sattn  = sscore + H_NUM * K_NB;    // [4][32]

    const int r   = blockIdx.x;
    const int tid = threadIdx.x;
    const int w    = tid >> 5;
    const int lane = tid & 31;

    // load e tile (16384 floats) + t (2048 floats), vectorized
    {
        const float4* eg = (const float4*)(e + (size_t)r * K_NB * D_TOT);
        float4* se4 = (float4*)se;
        #pragma unroll
        for (int i = 0; i < 16; i++) se4[tid + 256 * i] = eg[tid + 256 * i];
        const float4* tg = (const float4*)(t + (size_t)r * H_NUM * D_TOT);
        float4* st4 = (float4*)st;
        #pragma unroll
        for (int i = 0; i < 2; i++) st4[tid + 256 * i] = tg[tid + 256 * i];
    }
    __syncthreads();

    // scores: 128 (h,k) pairs; warp w handles 16 pairs
    #pragma unroll
    for (int pi = 0; pi < 16; pi++) {
        int p = w * 16 + pi;
        int h = p >> 5, k = p & 31;
        const float4* ek = (const float4*)(se + k * D_TOT);
        const float4* th = (const float4*)(st + h * D_TOT);
        float s = 0.f;
        #pragma unroll
        for (int i = 0; i < 4; i++) {
            float4 ev = ek[lane + 32 * i];
            float4 tv = th[lane + 32 * i];
            s += ev.x * tv.x + ev.y * tv.y + ev.z * tv.z + ev.w * tv.w;
        }
        #pragma unroll
        for (int o = 16; o; o >>= 1) s += __shfl_xor_sync(0xffffffffu, s, o);
        if (lane == 0) sscore[p] = s;
    }
    __syncthreads();

    // masked softmax over k: warp h handles head h (lane = k)
    if (w < H_NUM) {
        float s = (mask[(size_t)r * K_NB + lane] == 0) ? -1.0e9f : sscore[w * 32 + lane];
        float m = s;
        #pragma unroll
        for (int o = 16; o; o >>= 1) m = fmaxf(m, __shfl_xor_sync(0xffffffffu, m, o));
        float p = expf(s - m);
        float sum = p;
        #pragma unroll
        for (int o = 16; o; o >>= 1) sum += __shfl_xor_sync(0xffffffffu, sum, o);
        sattn[w * 32 + lane] = p / sum;
    }
    __syncthreads();

    // eb[h][d] = sum_k attn[h][k] * e[k][d]   (512 float4 outputs)
    float4* ebg = (float4*)(eb + (size_t)r * H_NUM * D_TOT);
    #pragma unroll
    for (int i = 0; i < 2; i++) {
        int idx = tid + 256 * i;        // float4 index in [4][128]
        int h   = idx >> 7;
        int d4  = idx & 127;
        float4 acc = make_float4(0.f, 0.f, 0.f, 0.f);
        #pragma unroll
        for (int k = 0; k < K_NB; k++) {
            float a = sattn[h * 32 + k];
            float4 ev = ((const float4*)(se + k * D_TOT))[d4];
            acc.x += a * ev.x; acc.y += a * ev.y;
            acc.z += a * ev.z; acc.w += a * ev.w;
        }
        ebg[idx] = acc;
    }
}

// ============================================================================
extern "C" void kernel_launch(void* const* d_in, const int* in_sizes, int n_in,
                              void* d_out, int out_size) {
    (void)in_sizes; (void)n_in; (void)out_size;
    const float* e    = (const float*)d_in[0];   // neibor_embedding [4,1024,32,512]
    const int*   mask = (const int*)  d_in[1];   // [4,1024,32]
    const float* x    = (const float*)d_in[2];   // [4,1024,512]
    const float* Wq   = (const float*)d_in[3];   // [512,512]
    const float* bq   = (const float*)d_in[4];   // [512]
    const float* Wk   = (const float*)d_in[5];   // [512,512]
    // d_in[6] = bk: provably softmax-invariant, unused
    const float* Wv   = (const float*)d_in[7];   // [512,512]
    const float* bv   = (const float*)d_in[8];   // [512]
    float* out = (float*)d_out;

    float *q, *t, *eb;
    cudaGetSymbolAddress((void**)&q,  g_q);
    cudaGetSymbolAddress((void**)&t,  g_t);
    cudaGetSymbolAddress((void**)&eb, g_eb);

    cudaFuncSetAttribute(attn_k, cudaFuncAttributeMaxDynamicSharedMemorySize, ATTN_SMEM);

    // 1) q = x @ Wq^T + bq              [4096,512] x [512,512]^T
    sgemm_k<true, true><<<dim3(32, 4, 1), 256>>>(
        x, D_TOT, 0,  Wq, D_TOT, 0,  q, D_TOT, 0,  bq, 0,  D_TOT);

    // 2) t_h = q_h @ Wk_h               per head: [4096,128] x [128,512]
    sgemm_k<false, false><<<dim3(32, 4, H_NUM), 256>>>(
        q, D_TOT, DH,  Wk, D_TOT, DH * D_TOT,  t, H_NUM * D_TOT, D_TOT,
        nullptr, 0,  DH);

    // 3) fused: scores -> masked softmax -> eb = attn @ e
    attn_k<<<R_TOT, 256, ATTN_SMEM>>>(e, mask, t, eb);

    // 4) out_h = eb_h @ Wv_h^T + bv_h   per head: [4096,512] x [128,512]^T
    sgemm_k<true, true><<<dim3(32, 1, H_NUM), 256>>>(
        eb, H_NUM * D_TOT, D_TOT,  Wv, D_TOT, DH * D_TOT,  out, D_TOT, DH,
        bv, DH,  D_TOT);
}

// round 4
// speedup vs baseline: 1.2198x; 1.2198x over previous
#include <cuda_runtime.h>
#include <cuda_bf16.h>
#include <cstdint>
#include <math.h>

#define R_TOT 4096
#define D_TOT 512
#define K_NB  32
#define H_NUM 4
#define DH    128

typedef __nv_bfloat16 bf16;
typedef unsigned int u32;

// ---------------- scratch (static device arrays; no allocation) ----------------
__device__ bf16 g_xh[R_TOT * D_TOT], g_xl[R_TOT * D_TOT];          // x split
__device__ bf16 g_qh[R_TOT * D_TOT], g_ql[R_TOT * D_TOT];          // q split
__device__ bf16 g_wqh[D_TOT * D_TOT], g_wql[D_TOT * D_TOT];        // Wq split
__device__ bf16 g_wkh[H_NUM * D_TOT * DH], g_wkl[H_NUM * D_TOT * DH]; // Wk^T split
__device__ bf16 g_wvh[D_TOT * D_TOT], g_wvl[D_TOT * D_TOT];        // Wv split
__device__ float g_t[R_TOT * H_NUM * D_TOT];                       // t fp32
__device__ bf16 g_ebh[R_TOT * H_NUM * D_TOT], g_ebl[R_TOT * H_NUM * D_TOT];

// ---------------- helpers ----------------
// permuted position of k within its 16-group so LDS.64 yields mma fragments:
// physical [4t..4t+3] holds original k {2t, 2t+1, 2t+8, 2t+9}
__device__ __forceinline__ int slot16(int k) {
    int t = k >> 1;
    return ((t & 3) << 2) | ((t >> 2) << 1) | (k & 1);
}
__device__ __forceinline__ u32 pkbf(bf16 a, bf16 b) {
    return (u32)__bfloat16_as_ushort(a) | ((u32)__bfloat16_as_ushort(b) << 16);
}
__device__ __forceinline__ void split1(float v, bf16& h, bf16& l) {
    h = __float2bfloat16_rn(v);
    l = __float2bfloat16_rn(v - __bfloat162float(h));
}
__device__ __forceinline__ void mma_bf(float* c, const u32* a, const u32* b) {
    asm volatile(
        "mma.sync.aligned.m16n8k16.row.col.f32.bf16.bf16.f32 "
        "{%0,%1,%2,%3},{%4,%5,%6,%7},{%8,%9},{%0,%1,%2,%3};"
        : "+f"(c[0]), "+f"(c[1]), "+f"(c[2]), "+f"(c[3])
        : "r"(a[0]), "r"(a[1]), "r"(a[2]), "r"(a[3]), "r"(b[0]), "r"(b[1]));
}
__device__ __forceinline__ void cp16(void* dst_smem, const void* src) {
    u32 d = (u32)__cvta_generic_to_shared(dst_smem);
    asm volatile("cp.async.ca.shared.global [%0], [%1], 16;" :: "r"(d), "l"(src));
}

// ---------------- prep: fp32 -> split bf16 (permuted k layout) ----------------
__global__ void split_prep(const float* __restrict__ src,
                           bf16* __restrict__ hi, bf16* __restrict__ lo, int n4) {
    int i = blockIdx.x * 256 + threadIdx.x;
    if (i >= n4) return;
    float4 v = reinterpret_cast<const float4*>(src)[i];
    int col = i << 2;
    int gb = col & ~15, cl = col & 15;
    int s0 = slot16(cl), s1 = slot16(cl + 2);
    bf16 h0,h1,h2,h3,l0,l1,l2,l3;
    split1(v.x,h0,l0); split1(v.y,h1,l1); split1(v.z,h2,l2); split1(v.w,h3,l3);
    *(u32*)(hi + gb + s0) = pkbf(h0,h1);
    *(u32*)(hi + gb + s1) = pkbf(h2,h3);
    *(u32*)(lo + gb + s0) = pkbf(l0,l1);
    *(u32*)(lo + gb + s1) = pkbf(l2,l3);
}

// Wk [512,512] -> per-head transposed split: wkt[h][n][k] = Wk[h*128+k][n]
__global__ void wkt_prep(const float* __restrict__ Wk,
                         bf16* __restrict__ hi, bf16* __restrict__ lo) {
    int idx = blockIdx.x * 256 + threadIdx.x;       // 65536 total
    int h = idx >> 14;
    int k0 = ((idx >> 9) & 31) << 2;
    int n = idx & 511;
    float v0 = Wk[(h*128 + k0 + 0) * 512 + n];
    float v1 = Wk[(h*128 + k0 + 1) * 512 + n];
    float v2 = Wk[(h*128 + k0 + 2) * 512 + n];
    float v3 = Wk[(h*128 + k0 + 3) * 512 + n];
    size_t base = (size_t)h * (512*128) + (size_t)n * 128 + (k0 & ~15);
    int s0 = slot16(k0 & 15), s1 = slot16((k0 & 15) + 2);
    bf16 h0,h1,h2,h3,l0,l1,l2,l3;
    split1(v0,h0,l0); split1(v1,h1,l1); split1(v2,h2,l2); split1(v3,h3,l3);
    *(u32*)(hi + base + s0) = pkbf(h0,h1);
    *(u32*)(hi + base + s1) = pkbf(h2,h3);
    *(u32*)(lo + base + s0) = pkbf(l0,l1);
    *(u32*)(lo + base + s1) = pkbf(l2,l3);
}

// ---------------- bf16x3 tensor-core GEMM ----------------
// C[m,n] = sum_k A[m,k]*BT[n,k] (+bias[n]); CTA tile 128(M)x64(N), K-chunk 16.
struct SB {
    bf16 Ah[128][16]; bf16 Al[128][16];
    bf16 Bh[64][16];  bf16 Bl[64][16];
};

template<bool BIAS, bool SPLIT>
__global__ void __launch_bounds__(256) gemm_bf16x3(
    const bf16* __restrict__ Ahi, const bf16* __restrict__ Alo, int lda, int aZ,
    const bf16* __restrict__ Bhi, const bf16* __restrict__ Blo, int ldb, int bZ,
    float* __restrict__ C, bf16* __restrict__ Chi, bf16* __restrict__ Clo,
    int ldc, int cZ, const float* __restrict__ bias, int biasZ, int Kd)
{
    __shared__ SB sb[2];

    const int tid = threadIdx.x;
    const int bm = blockIdx.x * 128;
    const int bn = blockIdx.y * 64;
    Ahi += (size_t)blockIdx.z * aZ;  Alo += (size_t)blockIdx.z * aZ;
    Bhi += (size_t)blockIdx.z * bZ;  Blo += (size_t)blockIdx.z * bZ;

    const int w = tid >> 5, lane = tid & 31;
    const int g = lane >> 2, tg = lane & 3;
    const int m0 = w * 16;

    const int sm = tid >> 1;           // 0..127
    const int hf = (tid & 1) * 8;      // 0 or 8 (bf16 elems)

    float acc[8][4];
    #pragma unroll
    for (int nt = 0; nt < 8; nt++)
        #pragma unroll
        for (int j = 0; j < 4; j++) acc[nt][j] = 0.f;

    const int NC = Kd >> 4;

    auto issue = [&](int kc, int bi) {
        size_t ka = (size_t)(bm + sm) * lda + kc * 16 + hf;
        cp16(&sb[bi].Ah[sm][hf], Ahi + ka);
        cp16(&sb[bi].Al[sm][hf], Alo + ka);
        if (tid < 128) {
            size_t kb = (size_t)(bn + sm) * ldb + kc * 16 + hf;
            cp16(&sb[bi].Bh[sm][hf], Bhi + kb);
            cp16(&sb[bi].Bl[sm][hf], Blo + kb);
        }
        asm volatile("cp.async.commit_group;");
    };

    issue(0, 0);
    for (int c = 0; c < NC; ++c) {
        if (c + 1 < NC) {
            issue(c + 1, (c + 1) & 1);
            asm volatile("cp.async.wait_group 1;");
        } else {
            asm volatile("cp.async.wait_group 0;");
        }
        __syncthreads();

        SB& S = sb[c & 1];
        u32 aH[4], aL[4];
        {
            uint2 x1 = *reinterpret_cast<const uint2*>(&S.Ah[m0 + g][tg * 4]);
            uint2 x2 = *reinterpret_cast<const uint2*>(&S.Ah[m0 + g + 8][tg * 4]);
            aH[0] = x1.x; aH[1] = x2.x; aH[2] = x1.y; aH[3] = x2.y;
            uint2 y1 = *reinterpret_cast<const uint2*>(&S.Al[m0 + g][tg * 4]);
            uint2 y2 = *reinterpret_cast<const uint2*>(&S.Al[m0 + g + 8][tg * 4]);
            aL[0] = y1.x; aL[1] = y2.x; aL[2] = y1.y; aL[3] = y2.y;
        }
        uint2 bH[8], bL[8];
        #pragma unroll
        for (int nt = 0; nt < 8; nt++)
            bH[nt] = *reinterpret_cast<const uint2*>(&S.Bh[nt * 8 + g][tg * 4]);
        #pragma unroll
        for (int nt = 0; nt < 8; nt++) mma_bf(acc[nt], aH, (const u32*)&bH[nt]);
        #pragma unroll
        for (int nt = 0; nt < 8; nt++) mma_bf(acc[nt], aL, (const u32*)&bH[nt]);
        #pragma unroll
        for (int nt = 0; nt < 8; nt++)
            bL[nt] = *reinterpret_cast<const uint2*>(&S.Bl[nt * 8 + g][tg * 4]);
        #pragma unroll
        for (int nt = 0; nt < 8; nt++) mma_bf(acc[nt], aH, (const u32*)&bL[nt]);
        __syncthreads();
    }

    // ---- epilogue ----
    const int row0 = bm + m0 + g;
    const int row1 = row0 + 8;
    #pragma unroll
    for (int nt = 0; nt < 8; nt++) {
        int col = bn + nt * 8 + tg * 2;
        float b0 = 0.f, b1 = 0.f;
        if (BIAS) {
            const float* bp = bias + (size_t)blockIdx.z * biasZ;
            b0 = bp[col]; b1 = bp[col + 1];
        }
        float v00 = acc[nt][0] + b0, v01 = acc[nt][1] + b1;
        float v10 = acc[nt][2] + b0, v11 = acc[nt][3] + b1;
        if (!SPLIT) {
            float* Cp = C + (size_t)blockIdx.z * cZ;
            *(float2*)&Cp[(size_t)row0 * ldc + col] = make_float2(v00, v01);
            *(float2*)&Cp[(size_t)row1 * ldc + col] = make_float2(v10, v11);
        } else {
            int gb = col & ~15, s = slot16(col & 15);
            bf16 h0,h1,l0,l1;
            split1(v00,h0,l0); split1(v01,h1,l1);
            *(u32*)(Chi + (size_t)row0 * ldc + gb + s) = pkbf(h0,h1);
            *(u32*)(Clo + (size_t)row0 * ldc + gb + s) = pkbf(l0,l1);
            split1(v10,h0,l0); split1(v11,h1,l1);
            *(u32*)(Chi + (size_t)row1 * ldc + gb + s) = pkbf(h0,h1);
            *(u32*)(Clo + (size_t)row1 * ldc + gb + s) = pkbf(l0,l1);
        }
    }
}

// ---------------- fused attention: scores -> masked softmax -> eb (split out) --
#define ATTN_SMEM (K_NB * D_TOT * 4 + H_NUM * D_TOT * 4 + H_NUM * K_NB * 4 * 2)

__global__ void __launch_bounds__(256) attn_k(
    const float* __restrict__ e,     // [R, 32, 512]
    const int*   __restrict__ mask,  // [R, 32]
    const float* __restrict__ t,     // [R, 4, 512] fp32
    bf16*        __restrict__ ebh,   // [R, 2048] split, permuted
    bf16*        __restrict__ ebl)
{
    extern __shared__ float sm[];
    float* se     = sm;
    float* st     = se + K_NB * D_TOT;
    float* sscore = st + H_NUM * D_TOT;
    float* sattn  = sscore + H_NUM * K_NB;

    const int r = blockIdx.x;
    const int tid = threadIdx.x;
    const int w = tid >> 5, lane = tid & 31;

    {
        const float4* eg = (const float4*)(e + (size_t)r * K_NB * D_TOT);
        float4* se4 = (float4*)se;
        #pragma unroll
        for (int i = 0; i < 16; i++) se4[tid + 256 * i] = eg[tid + 256 * i];
        const float4* tg4 = (const float4*)(t + (size_t)r * H_NUM * D_TOT);
        float4* st4 = (float4*)st;
        #pragma unroll
        for (int i = 0; i < 2; i++) st4[tid + 256 * i] = tg4[tid + 256 * i];
    }
    __syncthreads();

    #pragma unroll
    for (int pi = 0; pi < 16; pi++) {
        int p = w * 16 + pi;
        int h = p >> 5, k = p & 31;
        const float4* ek = (const float4*)(se + k * D_TOT);
        const float4* th = (const float4*)(st + h * D_TOT);
        float s = 0.f;
        #pragma unroll
        for (int i = 0; i < 4; i++) {
            float4 ev = ek[lane + 32 * i];
            float4 tv = th[lane + 32 * i];
            s += ev.x * tv.x + ev.y * tv.y + ev.z * tv.z + ev.w * tv.w;
        }
        #pragma unroll
        for (int o = 16; o; o >>= 1) s += __shfl_xor_sync(0xffffffffu, s, o);
        if (lane == 0) sscore[p] = s;
    }
    __syncthreads();

    if (w < H_NUM) {
        float s = (mask[(size_t)r * K_NB + lane] == 0) ? -1.0e9f : sscore[w * 32 + lane];
        float m = s;
        #pragma unroll
        for (int o = 16; o; o >>= 1) m = fmaxf(m, __shfl_xor_sync(0xffffffffu, m, o));
        float p = expf(s - m);
        float sum = p;
        #pragma unroll
        for (int o = 16; o; o >>= 1) sum += __shfl_xor_sync(0xffffffffu, sum, o);
        sattn[w * 32 + lane] = p / sum;
    }
    __syncthreads();

    #pragma unroll
    for (int i = 0; i < 2; i++) {
        int idx = tid + 256 * i;
        int h = idx >> 7, d4 = idx & 127;
        float4 acc = make_float4(0.f, 0.f, 0.f, 0.f);
        #pragma unroll
        for (int k = 0; k < K_NB; k++) {
            float a = sattn[h * 32 + k];
            float4 ev = ((const float4*)(se + k * D_TOT))[d4];
            acc.x += a * ev.x; acc.y += a * ev.y;
            acc.z += a * ev.z; acc.w += a * ev.w;
        }
        int col = idx << 2;
        int gb = col & ~15, cl = col & 15;
        int s0 = slot16(cl), s1 = slot16(cl + 2);
        bf16 h0,h1,h2,h3,l0,l1,l2,l3;
        split1(acc.x,h0,l0); split1(acc.y,h1,l1);
        split1(acc.z,h2,l2); split1(acc.w,h3,l3);
        size_t rb = (size_t)r * (H_NUM * D_TOT);
        *(u32*)(ebh + rb + gb + s0) = pkbf(h0,h1);
        *(u32*)(ebh + rb + gb + s1) = pkbf(h2,h3);
        *(u32*)(ebl + rb + gb + s0) = pkbf(l0,l1);
        *(u32*)(ebl + rb + gb + s1) = pkbf(l2,l3);
    }
}

// ============================================================================
extern "C" void kernel_launch(void* const* d_in, const int* in_sizes, int n_in,
                              void* d_out, int out_size) {
    (void)in_sizes; (void)n_in; (void)out_size;
    const float* e    = (const float*)d_in[0];
    const int*   mask = (const int*)  d_in[1];
    const float* x    = (const float*)d_in[2];
    const float* Wq   = (const float*)d_in[3];
    const float* bq   = (const float*)d_in[4];
    const float* Wk   = (const float*)d_in[5];
    // d_in[6] = bk: softmax-invariant, unused
    const float* Wv   = (const float*)d_in[7];
    const float* bv   = (const float*)d_in[8];
    float* out = (float*)d_out;

    bf16 *xh,*xl,*qh,*ql,*wqh,*wql,*wkh,*wkl,*wvh,*wvl,*ebh,*ebl;
    float *t;
    cudaGetSymbolAddress((void**)&xh,  g_xh);  cudaGetSymbolAddress((void**)&xl,  g_xl);
    cudaGetSymbolAddress((void**)&qh,  g_qh);  cudaGetSymbolAddress((void**)&ql,  g_ql);
    cudaGetSymbolAddress((void**)&wqh, g_wqh); cudaGetSymbolAddress((void**)&wql, g_wql);
    cudaGetSymbolAddress((void**)&wkh, g_wkh); cudaGetSymbolAddress((void**)&wkl, g_wkl);
    cudaGetSymbolAddress((void**)&wvh, g_wvh); cudaGetSymbolAddress((void**)&wvl, g_wvl);
    cudaGetSymbolAddress((void**)&ebh, g_ebh); cudaGetSymbolAddress((void**)&ebl, g_ebl);
    cudaGetSymbolAddress((void**)&t,   g_t);

    cudaFuncSetAttribute(attn_k, cudaFuncAttributeMaxDynamicSharedMemorySize, ATTN_SMEM);

    // prep: splits (+ Wk transpose)
    split_prep<<<(R_TOT * D_TOT / 4 + 255) / 256, 256>>>(x,  xh,  xl,  R_TOT * D_TOT / 4);
    split_prep<<<(D_TOT * D_TOT / 4 + 255) / 256, 256>>>(Wq, wqh, wql, D_TOT * D_TOT / 4);
    split_prep<<<(D_TOT * D_TOT / 4 + 255) / 256, 256>>>(Wv, wvh, wvl, D_TOT * D_TOT / 4);
    wkt_prep<<<H_NUM * DH * D_TOT / 4 / 256, 256>>>(Wk, wkh, wkl);

    // 1) q = x @ Wq^T + bq  -> split output
    gemm_bf16x3<true, true><<<dim3(32, 8, 1), 256>>>(
        xh, xl, D_TOT, 0,  wqh, wql, D_TOT, 0,
        nullptr, qh, ql, D_TOT, 0,  bq, 0,  D_TOT);

    // 2) t_h = q_h @ WkT_h^T  (fp32 out)
    gemm_bf16x3<false, false><<<dim3(32, 8, H_NUM), 256>>>(
        qh, ql, D_TOT, DH,  wkh, wkl, DH, D_TOT * DH,
        t, nullptr, nullptr, H_NUM * D_TOT, D_TOT,  nullptr, 0,  DH);

    // 3) fused attention -> eb split
    attn_k<<<R_TOT, 256, ATTN_SMEM>>>(e, mask, t, ebh, ebl);

    // 4) out_h = eb_h @ Wv_h^T + bv_h
    gemm_bf16x3<true, false><<<dim3(32, 2, H_NUM), 256>>>(
        ebh, ebl, H_NUM * D_TOT, D_TOT,  wvh, wvl, D_TOT, DH * D_TOT,
        out, nullptr, nullptr, D_TOT, DH,  bv, DH,  D_TOT);
}

// round 5
// speedup vs baseline: 1.4380x; 1.1789x over previous
#include <cuda_runtime.h>
#include <cuda_bf16.h>
#include <cstdint>
#include <math.h>

#define R_TOT 4096
#define D_TOT 512
#define K_NB  32
#define H_NUM 4
#define DH    128

typedef __nv_bfloat16 bf16;
typedef unsigned int u32;

// ---------------- scratch (static device arrays; no allocation) ----------------
__device__ bf16 g_xh[R_TOT * D_TOT], g_xl[R_TOT * D_TOT];
__device__ bf16 g_qh[R_TOT * D_TOT], g_ql[R_TOT * D_TOT];
__device__ bf16 g_wqh[D_TOT * D_TOT], g_wql[D_TOT * D_TOT];
__device__ bf16 g_wkh[H_NUM * D_TOT * DH], g_wkl[H_NUM * D_TOT * DH];
__device__ bf16 g_wvh[D_TOT * D_TOT], g_wvl[D_TOT * D_TOT];
__device__ float g_t[R_TOT * H_NUM * D_TOT];
__device__ bf16 g_ebh[R_TOT * H_NUM * D_TOT], g_ebl[R_TOT * H_NUM * D_TOT];

// ---------------- helpers ----------------
// permuted position of k within its 16-group so LDS.64 yields mma fragments:
// physical [4t..4t+3] holds original k {2t, 2t+1, 2t+8, 2t+9}
__device__ __forceinline__ int slot16(int k) {
    int t = k >> 1;
    return ((t & 3) << 2) | ((t >> 2) << 1) | (k & 1);
}
__device__ __forceinline__ u32 pkbf(bf16 a, bf16 b) {
    return (u32)__bfloat16_as_ushort(a) | ((u32)__bfloat16_as_ushort(b) << 16);
}
__device__ __forceinline__ void split1(float v, bf16& h, bf16& l) {
    h = __float2bfloat16_rn(v);
    l = __float2bfloat16_rn(v - __bfloat162float(h));
}
__device__ __forceinline__ void mma_bf(float* c, const u32* a, const u32* b) {
    asm volatile(
        "mma.sync.aligned.m16n8k16.row.col.f32.bf16.bf16.f32 "
        "{%0,%1,%2,%3},{%4,%5,%6,%7},{%8,%9},{%0,%1,%2,%3};"
        : "+f"(c[0]), "+f"(c[1]), "+f"(c[2]), "+f"(c[3])
        : "r"(a[0]), "r"(a[1]), "r"(a[2]), "r"(a[3]), "r"(b[0]), "r"(b[1]));
}
__device__ __forceinline__ void cp16(void* dst_smem, const void* src) {
    u32 d = (u32)__cvta_generic_to_shared(dst_smem);
    asm volatile("cp.async.ca.shared.global [%0], [%1], 16;" :: "r"(d), "l"(src));
}

// ---------------- merged prep: all fp32 -> split bf16 conversions ----------------
__device__ __forceinline__ void split4_store(float4 v, bf16* hi, bf16* lo, int col) {
    int gb = col & ~15, cl = col & 15;
    int s0 = slot16(cl), s1 = slot16(cl + 2);
    bf16 h0,h1,h2,h3,l0,l1,l2,l3;
    split1(v.x,h0,l0); split1(v.y,h1,l1); split1(v.z,h2,l2); split1(v.w,h3,l3);
    *(u32*)(hi + gb + s0) = pkbf(h0,h1);
    *(u32*)(hi + gb + s1) = pkbf(h2,h3);
    *(u32*)(lo + gb + s0) = pkbf(l0,l1);
    *(u32*)(lo + gb + s1) = pkbf(l2,l3);
}

// blocks [0,2048): x  [2048,2304): Wq  [2304,2560): Wv  [2560,2816): WkT
__global__ void __launch_bounds__(256) prep_all(
    const float* __restrict__ x,  bf16* __restrict__ xh,  bf16* __restrict__ xl,
    const float* __restrict__ Wq, bf16* __restrict__ wqh, bf16* __restrict__ wql,
    const float* __restrict__ Wv, bf16* __restrict__ wvh, bf16* __restrict__ wvl,
    const float* __restrict__ Wk, bf16* __restrict__ wkh, bf16* __restrict__ wkl)
{
    int blk = blockIdx.x;
    if (blk < 2560) {
        const float* src; bf16 *hi, *lo; int i;
        if (blk < 2048)      { src = x;  hi = xh;  lo = xl;  i = blk * 256 + threadIdx.x; }
        else if (blk < 2304) { src = Wq; hi = wqh; lo = wql; i = (blk - 2048) * 256 + threadIdx.x; }
        else                 { src = Wv; hi = wvh; lo = wvl; i = (blk - 2304) * 256 + threadIdx.x; }
        float4 v = reinterpret_cast<const float4*>(src)[i];
        split4_store(v, hi, lo, i << 2);
    } else {
        int idx = (blk - 2560) * 256 + threadIdx.x;   // 65536 total
        int h = idx >> 14;
        int k0 = ((idx >> 9) & 31) << 2;
        int n = idx & 511;
        float v0 = Wk[(h*128 + k0 + 0) * 512 + n];
        float v1 = Wk[(h*128 + k0 + 1) * 512 + n];
        float v2 = Wk[(h*128 + k0 + 2) * 512 + n];
        float v3 = Wk[(h*128 + k0 + 3) * 512 + n];
        size_t base = (size_t)h * (512*128) + (size_t)n * 128 + (k0 & ~15);
        int s0 = slot16(k0 & 15), s1 = slot16((k0 & 15) + 2);
        bf16 h0,h1,h2,h3,l0,l1,l2,l3;
        split1(v0,h0,l0); split1(v1,h1,l1); split1(v2,h2,l2); split1(v3,h3,l3);
        *(u32*)(wkh + base + s0) = pkbf(h0,h1);
        *(u32*)(wkh + base + s1) = pkbf(h2,h3);
        *(u32*)(wkl + base + s0) = pkbf(l0,l1);
        *(u32*)(wkl + base + s1) = pkbf(l2,l3);
    }
}

// ---------------- bf16x3 tensor-core GEMM (unchanged from R4, passing) ----------
struct SB {
    bf16 Ah[128][16]; bf16 Al[128][16];
    bf16 Bh[64][16];  bf16 Bl[64][16];
};

template<bool BIAS, bool SPLIT>
__global__ void __launch_bounds__(256) gemm_bf16x3(
    const bf16* __restrict__ Ahi, const bf16* __restrict__ Alo, int lda, int aZ,
    const bf16* __restrict__ Bhi, const bf16* __restrict__ Blo, int ldb, int bZ,
    float* __restrict__ C, bf16* __restrict__ Chi, bf16* __restrict__ Clo,
    int ldc, int cZ, const float* __restrict__ bias, int biasZ, int Kd)
{
    __shared__ SB sb[2];

    const int tid = threadIdx.x;
    const int bm = blockIdx.x * 128;
    const int bn = blockIdx.y * 64;
    Ahi += (size_t)blockIdx.z * aZ;  Alo += (size_t)blockIdx.z * aZ;
    Bhi += (size_t)blockIdx.z * bZ;  Blo += (size_t)blockIdx.z * bZ;

    const int w = tid >> 5, lane = tid & 31;
    const int g = lane >> 2, tg = lane & 3;
    const int m0 = w * 16;

    const int sm = tid >> 1;
    const int hf = (tid & 1) * 8;

    float acc[8][4];
    #pragma unroll
    for (int nt = 0; nt < 8; nt++)
        #pragma unroll
        for (int j = 0; j < 4; j++) acc[nt][j] = 0.f;

    const int NC = Kd >> 4;

    auto issue = [&](int kc, int bi) {
        size_t ka = (size_t)(bm + sm) * lda + kc * 16 + hf;
        cp16(&sb[bi].Ah[sm][hf], Ahi + ka);
        cp16(&sb[bi].Al[sm][hf], Alo + ka);
        if (tid < 128) {
            size_t kb = (size_t)(bn + sm) * ldb + kc * 16 + hf;
            cp16(&sb[bi].Bh[sm][hf], Bhi + kb);
            cp16(&sb[bi].Bl[sm][hf], Blo + kb);
        }
        asm volatile("cp.async.commit_group;");
    };

    issue(0, 0);
    for (int c = 0; c < NC; ++c) {
        if (c + 1 < NC) {
            issue(c + 1, (c + 1) & 1);
            asm volatile("cp.async.wait_group 1;");
        } else {
            asm volatile("cp.async.wait_group 0;");
        }
        __syncthreads();

        SB& S = sb[c & 1];
        u32 aH[4], aL[4];
        {
            uint2 x1 = *reinterpret_cast<const uint2*>(&S.Ah[m0 + g][tg * 4]);
            uint2 x2 = *reinterpret_cast<const uint2*>(&S.Ah[m0 + g + 8][tg * 4]);
            aH[0] = x1.x; aH[1] = x2.x; aH[2] = x1.y; aH[3] = x2.y;
            uint2 y1 = *reinterpret_cast<const uint2*>(&S.Al[m0 + g][tg * 4]);
            uint2 y2 = *reinterpret_cast<const uint2*>(&S.Al[m0 + g + 8][tg * 4]);
            aL[0] = y1.x; aL[1] = y2.x; aL[2] = y1.y; aL[3] = y2.y;
        }
        uint2 bH[8], bL[8];
        #pragma unroll
        for (int nt = 0; nt < 8; nt++)
            bH[nt] = *reinterpret_cast<const uint2*>(&S.Bh[nt * 8 + g][tg * 4]);
        #pragma unroll
        for (int nt = 0; nt < 8; nt++) mma_bf(acc[nt], aH, (const u32*)&bH[nt]);
        #pragma unroll
        for (int nt = 0; nt < 8; nt++) mma_bf(acc[nt], aL, (const u32*)&bH[nt]);
        #pragma unroll
        for (int nt = 0; nt < 8; nt++)
            bL[nt] = *reinterpret_cast<const uint2*>(&S.Bl[nt * 8 + g][tg * 4]);
        #pragma unroll
        for (int nt = 0; nt < 8; nt++) mma_bf(acc[nt], aH, (const u32*)&bL[nt]);
        __syncthreads();
    }

    const int row0 = bm + m0 + g;
    const int row1 = row0 + 8;
    #pragma unroll
    for (int nt = 0; nt < 8; nt++) {
        int col = bn + nt * 8 + tg * 2;
        float b0 = 0.f, b1 = 0.f;
        if (BIAS) {
            const float* bp = bias + (size_t)blockIdx.z * biasZ;
            b0 = bp[col]; b1 = bp[col + 1];
        }
        float v00 = acc[nt][0] + b0, v01 = acc[nt][1] + b1;
        float v10 = acc[nt][2] + b0, v11 = acc[nt][3] + b1;
        if (!SPLIT) {
            float* Cp = C + (size_t)blockIdx.z * cZ;
            *(float2*)&Cp[(size_t)row0 * ldc + col] = make_float2(v00, v01);
            *(float2*)&Cp[(size_t)row1 * ldc + col] = make_float2(v10, v11);
        } else {
            int gb = col & ~15, s = slot16(col & 15);
            bf16 h0,h1,l0,l1;
            split1(v00,h0,l0); split1(v01,h1,l1);
            *(u32*)(Chi + (size_t)row0 * ldc + gb + s) = pkbf(h0,h1);
            *(u32*)(Clo + (size_t)row0 * ldc + gb + s) = pkbf(l0,l1);
            split1(v10,h0,l0); split1(v11,h1,l1);
            *(u32*)(Chi + (size_t)row1 * ldc + gb + s) = pkbf(h0,h1);
            *(u32*)(Clo + (size_t)row1 * ldc + gb + s) = pkbf(l0,l1);
        }
    }
}

// ---------------- fused attention v2: low-LDS-traffic layout ----------------
// smem: se [32][512] f32 (64KB) + st [4][512] (8KB) + sscore[4][32] + sattnT[32][4]
#define ATTN_SMEM (K_NB * D_TOT * 4 + H_NUM * D_TOT * 4 + H_NUM * K_NB * 4 * 2)

__global__ void __launch_bounds__(256, 3) attn_k(
    const float* __restrict__ e,     // [R, 32, 512]
    const int*   __restrict__ mask,  // [R, 32]
    const float* __restrict__ t,     // [R, 4, 512] fp32
    bf16*        __restrict__ ebh,   // [R, 2048] split, permuted
    bf16*        __restrict__ ebl)
{
    extern __shared__ float smf[];
    float* se      = smf;                           // [32*512]
    float* st      = se + K_NB * D_TOT;             // [4*512]
    float* sscore  = st + H_NUM * D_TOT;            // [h][k] = h*32+k
    float* sattnT  = sscore + H_NUM * K_NB;         // [k][h] = k*4+h

    const int r = blockIdx.x;
    const int tid = threadIdx.x;
    const int w = tid >> 5, lane = tid & 31;

    // ---- load e (64KB) + t (8KB) ----
    {
        const float4* eg = (const float4*)(e + (size_t)r * K_NB * D_TOT);
        float4* se4 = (float4*)se;
        #pragma unroll
        for (int i = 0; i < 16; i++) se4[tid + 256 * i] = eg[tid + 256 * i];
        const float4* tg4 = (const float4*)(t + (size_t)r * H_NUM * D_TOT);
        float4* st4 = (float4*)st;
        #pragma unroll
        for (int i = 0; i < 2; i++) st4[tid + 256 * i] = tg4[tid + 256 * i];
    }
    __syncthreads();

    // ---- scores: warp covers 2 heads x 8 k's. One e read serves both heads. ----
    // w = hp*4 + kg : hp in {0,1} -> heads {2hp, 2hp+1}; kg in 0..3 -> k in [8kg, 8kg+8)
    {
        const int hp = w >> 2;
        const int h0 = hp * 2;
        const int k0 = (w & 3) * 8;
        // t for both heads in regs: dim float4-index = c*32 + lane
        float4 tR[2][4];
        const float4* st4 = (const float4*)st;
        #pragma unroll
        for (int hh = 0; hh < 2; hh++)
            #pragma unroll
            for (int c = 0; c < 4; c++)
                tR[hh][c] = st4[(h0 + hh) * 128 + c * 32 + lane];

        #pragma unroll
        for (int kk = 0; kk < 8; kk++) {
            int k = k0 + kk;
            const float4* ek = (const float4*)(se + k * D_TOT);
            float s0 = 0.f, s1 = 0.f;
            #pragma unroll
            for (int c = 0; c < 4; c++) {
                float4 ev = ek[c * 32 + lane];
                s0 += ev.x*tR[0][c].x + ev.y*tR[0][c].y + ev.z*tR[0][c].z + ev.w*tR[0][c].w;
                s1 += ev.x*tR[1][c].x + ev.y*tR[1][c].y + ev.z*tR[1][c].z + ev.w*tR[1][c].w;
            }
            #pragma unroll
            for (int o = 16; o; o >>= 1) {
                s0 += __shfl_xor_sync(0xffffffffu, s0, o);
                s1 += __shfl_xor_sync(0xffffffffu, s1, o);
            }
            if (lane == 0) {
                sscore[h0 * 32 + k]       = s0;
                sscore[(h0 + 1) * 32 + k] = s1;
            }
        }
    }
    __syncthreads();

    // ---- masked softmax: warp h handles head h (lane = k); output transposed [k][h] ----
    if (w < H_NUM) {
        float s = (mask[(size_t)r * K_NB + lane] == 0) ? -1.0e9f : sscore[w * 32 + lane];
        float m = s;
        #pragma unroll
        for (int o = 16; o; o >>= 1) m = fmaxf(m, __shfl_xor_sync(0xffffffffu, m, o));
        float p = expf(s - m);
        float sum = p;
        #pragma unroll
        for (int o = 16; o; o >>= 1) sum += __shfl_xor_sync(0xffffffffu, sum, o);
        sattnT[lane * 4 + w] = p / sum;
    }
    __syncthreads();

    // ---- aggregation: thread owns float2 column; one e read feeds all 4 heads ----
    {
        const float2* se2 = (const float2*)se;        // [k][256] float2
        const float4* at4 = (const float4*)sattnT;    // [k] -> 4 head weights
        float2 acc0 = {0,0}, acc1 = {0,0}, acc2 = {0,0}, acc3 = {0,0};
        #pragma unroll
        for (int k = 0; k < K_NB; k++) {
            float4 a = at4[k];                         // broadcast
            float2 ev = se2[k * 256 + tid];
            acc0.x += a.x * ev.x; acc0.y += a.x * ev.y;
            acc1.x += a.y * ev.x; acc1.y += a.y * ev.y;
            acc2.x += a.z * ev.x; acc2.y += a.z * ev.y;
            acc3.x += a.w * ev.x; acc3.y += a.w * ev.y;
        }
        // split-bf16 permuted write: head h at column offset h*512
        float2 accs[4] = {acc0, acc1, acc2, acc3};
        const size_t rb = (size_t)r * (H_NUM * D_TOT);
        const int col = tid * 2;                       // 0..510 within head
        const int gb = col & ~15;
        const int s0 = slot16(col & 15);               // even pair -> slots s0, s0+1
        #pragma unroll
        for (int h = 0; h < H_NUM; h++) {
            bf16 hh0,hh1,ll0,ll1;
            split1(accs[h].x, hh0, ll0);
            split1(accs[h].y, hh1, ll1);
            size_t base = rb + (size_t)h * D_TOT + gb + s0;
            *(u32*)(ebh + base) = pkbf(hh0, hh1);
            *(u32*)(ebl + base) = pkbf(ll0, ll1);
        }
    }
}

// ============================================================================
extern "C" void kernel_launch(void* const* d_in, const int* in_sizes, int n_in,
                              void* d_out, int out_size) {
    (void)in_sizes; (void)n_in; (void)out_size;
    const float* e    = (const float*)d_in[0];
    const int*   mask = (const int*)  d_in[1];
    const float* x    = (const float*)d_in[2];
    const float* Wq   = (const float*)d_in[3];
    const float* bq   = (const float*)d_in[4];
    const float* Wk   = (const float*)d_in[5];
    // d_in[6] = bk: softmax-invariant, unused
    const float* Wv   = (const float*)d_in[7];
    const float* bv   = (const float*)d_in[8];
    float* out = (float*)d_out;

    bf16 *xh,*xl,*qh,*ql,*wqh,*wql,*wkh,*wkl,*wvh,*wvl,*ebh,*ebl;
    float *t;
    cudaGetSymbolAddress((void**)&xh,  g_xh);  cudaGetSymbolAddress((void**)&xl,  g_xl);
    cudaGetSymbolAddress((void**)&qh,  g_qh);  cudaGetSymbolAddress((void**)&ql,  g_ql);
    cudaGetSymbolAddress((void**)&wqh, g_wqh); cudaGetSymbolAddress((void**)&wql, g_wql);
    cudaGetSymbolAddress((void**)&wkh, g_wkh); cudaGetSymbolAddress((void**)&wkl, g_wkl);
    cudaGetSymbolAddress((void**)&wvh, g_wvh); cudaGetSymbolAddress((void**)&wvl, g_wvl);
    cudaGetSymbolAddress((void**)&ebh, g_ebh); cudaGetSymbolAddress((void**)&ebl, g_ebl);
    cudaGetSymbolAddress((void**)&t,   g_t);

    cudaFuncSetAttribute(attn_k, cudaFuncAttributeMaxDynamicSharedMemorySize, ATTN_SMEM);

    // 0) merged prep: x/Wq/Wv splits + Wk transpose-split (one launch)
    prep_all<<<2816, 256>>>(x, xh, xl, Wq, wqh, wql, Wv, wvh, wvl, Wk, wkh, wkl);

    // 1) q = x @ Wq^T + bq  -> split output
    gemm_bf16x3<true, true><<<dim3(32, 8, 1), 256>>>(
        xh, xl, D_TOT, 0,  wqh, wql, D_TOT, 0,
        nullptr, qh, ql, D_TOT, 0,  bq, 0,  D_TOT);

    // 2) t_h = q_h @ WkT_h^T  (fp32 out)
    gemm_bf16x3<false, false><<<dim3(32, 8, H_NUM), 256>>>(
        qh, ql, D_TOT, DH,  wkh, wkl, DH, D_TOT * DH,
        t, nullptr, nullptr, H_NUM * D_TOT, D_TOT,  nullptr, 0,  DH);

    // 3) fused attention -> eb split
    attn_k<<<R_TOT, 256, ATTN_SMEM>>>(e, mask, t, ebh, ebl);

    // 4) out_h = eb_h @ Wv_h^T + bv_h
    gemm_bf16x3<true, false><<<dim3(32, 2, H_NUM), 256>>>(
        ebh, ebl, H_NUM * D_TOT, D_TOT,  wvh, wvl, D_TOT, DH * D_TOT,
        out, nullptr, nullptr, D_TOT, DH,  bv, DH,  D_TOT);
}

// round 9
// speedup vs baseline: 1.5970x; 1.1106x over previous
#include <cuda_runtime.h>
#include <cuda_bf16.h>
#include <cstdint>
#include <math.h>

#define R_TOT 4096
#define D_TOT 512
#define K_NB  32
#define H_NUM 4
#define DH    128
#define CH    8              // attn neighbor chunk
#define NCH   (K_NB / CH)    // 4 chunks

typedef __nv_bfloat16 bf16;
typedef unsigned int u32;

// ---------------- scratch ----------------
__device__ bf16 g_xh[R_TOT * D_TOT], g_xl[R_TOT * D_TOT];
__device__ bf16 g_qh[R_TOT * D_TOT], g_ql[R_TOT * D_TOT];
__device__ bf16 g_wqh[D_TOT * D_TOT], g_wql[D_TOT * D_TOT];
__device__ bf16 g_wkh[H_NUM * D_TOT * DH], g_wkl[H_NUM * D_TOT * DH];
__device__ bf16 g_wvh[D_TOT * D_TOT], g_wvl[D_TOT * D_TOT];
__device__ float g_t[R_TOT * H_NUM * D_TOT];
__device__ bf16 g_ebh[R_TOT * H_NUM * D_TOT], g_ebl[R_TOT * H_NUM * D_TOT];

// ---------------- helpers ----------------
__device__ __forceinline__ int slot16(int k) {
    int t = k >> 1;
    return ((t & 3) << 2) | ((t >> 2) << 1) | (k & 1);
}
__device__ __forceinline__ u32 pkbf(bf16 a, bf16 b) {
    return (u32)__bfloat16_as_ushort(a) | ((u32)__bfloat16_as_ushort(b) << 16);
}
__device__ __forceinline__ void split1(float v, bf16& h, bf16& l) {
    h = __float2bfloat16_rn(v);
    l = __float2bfloat16_rn(v - __bfloat162float(h));
}
__device__ __forceinline__ void mma_bf(float* c, const u32* a, const u32* b) {
    asm volatile(
        "mma.sync.aligned.m16n8k16.row.col.f32.bf16.bf16.f32 "
        "{%0,%1,%2,%3},{%4,%5,%6,%7},{%8,%9},{%0,%1,%2,%3};"
        : "+f"(c[0]), "+f"(c[1]), "+f"(c[2]), "+f"(c[3])
        : "r"(a[0]), "r"(a[1]), "r"(a[2]), "r"(a[3]), "r"(b[0]), "r"(b[1]));
}
__device__ __forceinline__ void cp16(void* dst_smem, const void* src) {
    u32 d = (u32)__cvta_generic_to_shared(dst_smem);
    asm volatile("cp.async.ca.shared.global [%0], [%1], 16;" :: "r"(d), "l"(src));
}

// ---------------- merged prep ----------------
__device__ __forceinline__ void split4_store(float4 v, bf16* hi, bf16* lo, int col) {
    int gb = col & ~15, cl = col & 15;
    int s0 = slot16(cl), s1 = slot16(cl + 2);
    bf16 h0,h1,h2,h3,l0,l1,l2,l3;
    split1(v.x,h0,l0); split1(v.y,h1,l1); split1(v.z,h2,l2); split1(v.w,h3,l3);
    *(u32*)(hi + gb + s0) = pkbf(h0,h1);
    *(u32*)(hi + gb + s1) = pkbf(h2,h3);
    *(u32*)(lo + gb + s0) = pkbf(l0,l1);
    *(u32*)(lo + gb + s1) = pkbf(l2,l3);
}

__global__ void __launch_bounds__(256) prep_all(
    const float* __restrict__ x,  bf16* __restrict__ xh,  bf16* __restrict__ xl,
    const float* __restrict__ Wq, bf16* __restrict__ wqh, bf16* __restrict__ wql,
    const float* __restrict__ Wv, bf16* __restrict__ wvh, bf16* __restrict__ wvl,
    const float* __restrict__ Wk, bf16* __restrict__ wkh, bf16* __restrict__ wkl)
{
    int blk = blockIdx.x;
    if (blk < 2560) {
        const float* src; bf16 *hi, *lo; int i;
        if (blk < 2048)      { src = x;  hi = xh;  lo = xl;  i = blk * 256 + threadIdx.x; }
        else if (blk < 2304) { src = Wq; hi = wqh; lo = wql; i = (blk - 2048) * 256 + threadIdx.x; }
        else                 { src = Wv; hi = wvh; lo = wvl; i = (blk - 2304) * 256 + threadIdx.x; }
        float4 v = reinterpret_cast<const float4*>(src)[i];
        split4_store(v, hi, lo, i << 2);
    } else {
        int idx = (blk - 2560) * 256 + threadIdx.x;
        int h = idx >> 14;
        int k0 = ((idx >> 9) & 31) << 2;
        int n = idx & 511;
        float v0 = Wk[(h*128 + k0 + 0) * 512 + n];
        float v1 = Wk[(h*128 + k0 + 1) * 512 + n];
        float v2 = Wk[(h*128 + k0 + 2) * 512 + n];
        float v3 = Wk[(h*128 + k0 + 3) * 512 + n];
        size_t base = (size_t)h * (512*128) + (size_t)n * 128 + (k0 & ~15);
        int s0 = slot16(k0 & 15), s1 = slot16((k0 & 15) + 2);
        bf16 h0,h1,h2,h3,l0,l1,l2,l3;
        split1(v0,h0,l0); split1(v1,h1,l1); split1(v2,h2,l2); split1(v3,h3,l3);
        *(u32*)(wkh + base + s0) = pkbf(h0,h1);
        *(u32*)(wkh + base + s1) = pkbf(h2,h3);
        *(u32*)(wkl + base + s0) = pkbf(l0,l1);
        *(u32*)(wkl + base + s1) = pkbf(l2,l3);
    }
}

// ---------------- bf16x3 tensor-core GEMM (4 buffers, 2 chunks per sync) ------
struct SB {
    bf16 Ah[128][16]; bf16 Al[128][16];
    bf16 Bh[64][16];  bf16 Bl[64][16];
};

template<bool BIAS, bool SPLIT>
__global__ void __launch_bounds__(256) gemm_bf16x3(
    const bf16* __restrict__ Ahi, const bf16* __restrict__ Alo, int lda, int aZ,
    const bf16* __restrict__ Bhi, const bf16* __restrict__ Blo, int ldb, int bZ,
    float* __restrict__ C, bf16* __restrict__ Chi, bf16* __restrict__ Clo,
    int ldc, int cZ, const float* __restrict__ bias, int biasZ, int Kd)
{
    __shared__ SB sb[4];

    const int tid = threadIdx.x;
    const int bm = blockIdx.x * 128;
    const int bn = blockIdx.y * 64;
    Ahi += (size_t)blockIdx.z * aZ;  Alo += (size_t)blockIdx.z * aZ;
    Bhi += (size_t)blockIdx.z * bZ;  Blo += (size_t)blockIdx.z * bZ;

    const int w = tid >> 5, lane = tid & 31;
    const int g = lane >> 2, tg = lane & 3;
    const int m0 = w * 16;

    const int sm = tid >> 1;
    const int hf = (tid & 1) * 8;

    float acc[8][4];
    #pragma unroll
    for (int nt = 0; nt < 8; nt++)
        #pragma unroll
        for (int j = 0; j < 4; j++) acc[nt][j] = 0.f;

    const int NP = Kd >> 5;   // pairs of k16 chunks

    auto issue = [&](int kc, int bi) {
        size_t ka = (size_t)(bm + sm) * lda + kc * 16 + hf;
        cp16(&sb[bi].Ah[sm][hf], Ahi + ka);
        cp16(&sb[bi].Al[sm][hf], Alo + ka);
        if (tid < 128) {
            size_t kb = (size_t)(bn + sm) * ldb + kc * 16 + hf;
            cp16(&sb[bi].Bh[sm][hf], Bhi + kb);
            cp16(&sb[bi].Bl[sm][hf], Blo + kb);
        }
        asm volatile("cp.async.commit_group;");
    };

    issue(0, 0); issue(1, 1);
    for (int p = 0; p < NP; ++p) {
        if (p + 1 < NP) {
            int base = 2 * ((p + 1) & 1);
            issue(2 * (p + 1), base); issue(2 * (p + 1) + 1, base + 1);
            asm volatile("cp.async.wait_group 2;");
        } else {
            asm volatile("cp.async.wait_group 0;");
        }
        __syncthreads();

        #pragma unroll
        for (int sub = 0; sub < 2; sub++) {
            SB& S = sb[2 * (p & 1) + sub];
            u32 aH[4], aL[4];
            {
                uint2 x1 = *reinterpret_cast<const uint2*>(&S.Ah[m0 + g][tg * 4]);
                uint2 x2 = *reinterpret_cast<const uint2*>(&S.Ah[m0 + g + 8][tg * 4]);
                aH[0] = x1.x; aH[1] = x2.x; aH[2] = x1.y; aH[3] = x2.y;
                uint2 y1 = *reinterpret_cast<const uint2*>(&S.Al[m0 + g][tg * 4]);
                uint2 y2 = *reinterpret_cast<const uint2*>(&S.Al[m0 + g + 8][tg * 4]);
                aL[0] = y1.x; aL[1] = y2.x; aL[2] = y1.y; aL[3] = y2.y;
            }
            uint2 bH[8], bL[8];
            #pragma unroll
            for (int nt = 0; nt < 8; nt++)
                bH[nt] = *reinterpret_cast<const uint2*>(&S.Bh[nt * 8 + g][tg * 4]);
            #pragma unroll
            for (int nt = 0; nt < 8; nt++) mma_bf(acc[nt], aH, (const u32*)&bH[nt]);
            #pragma unroll
            for (int nt = 0; nt < 8; nt++) mma_bf(acc[nt], aL, (const u32*)&bH[nt]);
            #pragma unroll
            for (int nt = 0; nt < 8; nt++)
                bL[nt] = *reinterpret_cast<const uint2*>(&S.Bl[nt * 8 + g][tg * 4]);
            #pragma unroll
            for (int nt = 0; nt < 8; nt++) mma_bf(acc[nt], aH, (const u32*)&bL[nt]);
        }
        __syncthreads();
    }

    const int row0 = bm + m0 + g;
    const int row1 = row0 + 8;
    #pragma unroll
    for (int nt = 0; nt < 8; nt++) {
        int col = bn + nt * 8 + tg * 2;
        float b0 = 0.f, b1 = 0.f;
        if (BIAS) {
            const float* bp = bias + (size_t)blockIdx.z * biasZ;
            b0 = bp[col]; b1 = bp[col + 1];
        }
        float v00 = acc[nt][0] + b0, v01 = acc[nt][1] + b1;
        float v10 = acc[nt][2] + b0, v11 = acc[nt][3] + b1;
        if (!SPLIT) {
            float* Cp = C + (size_t)blockIdx.z * cZ;
            *(float2*)&Cp[(size_t)row0 * ldc + col] = make_float2(v00, v01);
            *(float2*)&Cp[(size_t)row1 * ldc + col] = make_float2(v10, v11);
        } else {
            int gb = col & ~15, s = slot16(col & 15);
            bf16 h0,h1,l0,l1;
            split1(v00,h0,l0); split1(v01,h1,l1);
            *(u32*)(Chi + (size_t)row0 * ldc + gb + s) = pkbf(h0,h1);
            *(u32*)(Clo + (size_t)row0 * ldc + gb + s) = pkbf(l0,l1);
            split1(v10,h0,l0); split1(v11,h1,l1);
            *(u32*)(Chi + (size_t)row1 * ldc + gb + s) = pkbf(h0,h1);
            *(u32*)(Clo + (size_t)row1 * ldc + gb + s) = pkbf(l0,l1);
        }
    }
}

// ---------------- flash-chunked attention ----------------
// Per CTA (row r): 4 chunks of 8 neighbors, cp.async double buffer.
// Online softmax per head in warps 0-3; acc per thread = float2 col x 4 heads.
__global__ void __launch_bounds__(256, 4) attn_k(
    const float* __restrict__ e,     // [R, 32, 512]
    const int*   __restrict__ mask,  // [R, 32]
    const float* __restrict__ t,     // [R, 4, 512] fp32
    bf16*        __restrict__ ebh,
    bf16*        __restrict__ ebl)
{
    __shared__ float ebuf[2][CH * D_TOT];          // 2 x 16KB
    __shared__ float sscore[H_NUM * CH];           // [h][k]
    __shared__ __align__(16) float sp[CH * H_NUM]; // [k][h]
    __shared__ float salpha[H_NUM];
    __shared__ float ssum[H_NUM];
    __shared__ int   smask[K_NB];

    const int r = blockIdx.x;
    const int tid = threadIdx.x;
    const int w = tid >> 5, lane = tid & 31;

    const float* eg = e + (size_t)r * K_NB * D_TOT;

    auto issue = [&](int c, int bi) {
        #pragma unroll
        for (int j = 0; j < 4; j++) {
            int u = tid + 256 * j;                 // 16B unit
            cp16(&ebuf[bi][u * 4], eg + (size_t)c * (CH * D_TOT) + u * 4);
        }
        asm volatile("cp.async.commit_group;");
    };

    issue(0, 0); issue(1, 1);
    if (tid < K_NB) smask[tid] = mask[(size_t)r * K_NB + tid];

    // t for this warp's 2 heads, in registers
    const int hp = w >> 2;          // 0,1 -> heads {2hp, 2hp+1}
    const int h0 = hp * 2;
    const int kw = (w & 3) * 2;     // this warp scores k in {kw, kw+1}
    float4 tR[2][4];
    {
        const float4* tg0 = (const float4*)(t + (size_t)r * (H_NUM*D_TOT) + (size_t)h0 * D_TOT);
        const float4* tg1 = (const float4*)(t + (size_t)r * (H_NUM*D_TOT) + (size_t)(h0+1) * D_TOT);
        #pragma unroll
        for (int ci = 0; ci < 4; ci++) { tR[0][ci] = tg0[ci*32 + lane]; tR[1][ci] = tg1[ci*32 + lane]; }
    }

    float2 acc[H_NUM];
    #pragma unroll
    for (int h = 0; h < H_NUM; h++) acc[h] = make_float2(0.f, 0.f);
    float mRun = -INFINITY, sRun = 0.f;           // used by warps 0-3 (head = w)

    for (int c = 0; c < NCH; c++) {
        if (c == NCH - 1) { asm volatile("cp.async.wait_group 0;"); }
        else              { asm volatile("cp.async.wait_group 1;"); }
        __syncthreads();
        const float* E = ebuf[c & 1];

        // ---- scores: warp covers 2 heads x 2 k ----
        #pragma unroll
        for (int kk = 0; kk < 2; kk++) {
            int k = kw + kk;
            const float4* ek = (const float4*)(E + k * D_TOT);
            float s0 = 0.f, s1 = 0.f;
            #pragma unroll
            for (int ci = 0; ci < 4; ci++) {
                float4 ev = ek[ci*32 + lane];
                s0 += ev.x*tR[0][ci].x + ev.y*tR[0][ci].y + ev.z*tR[0][ci].z + ev.w*tR[0][ci].w;
                s1 += ev.x*tR[1][ci].x + ev.y*tR[1][ci].y + ev.z*tR[1][ci].z + ev.w*tR[1][ci].w;
            }
            #pragma unroll
            for (int o = 16; o; o >>= 1) {
                s0 += __shfl_xor_sync(0xffffffffu, s0, o);
                s1 += __shfl_xor_sync(0xffffffffu, s1, o);
            }
            if (lane == 0) {
                sscore[h0 * CH + k]       = s0;
                sscore[(h0 + 1) * CH + k] = s1;
            }
        }
        __syncthreads();

        // ---- online softmax update: warp h = w (w < 4) ----
        if (w < H_NUM) {
            float sc = -INFINITY;
            if (lane < CH) {
                sc = sscore[w * CH + lane];
                if (smask[c * CH + lane] == 0) sc = -1.0e9f;
            }
            float cmax = sc;
            #pragma unroll
            for (int o = 16; o; o >>= 1) cmax = fmaxf(cmax, __shfl_xor_sync(0xffffffffu, cmax, o));
            float mNew = fmaxf(mRun, cmax);
            float alpha = expf(mRun - mNew);          // 0 on first chunk
            float p = (lane < CH) ? expf(sc - mNew) : 0.f;
            float psum = p;
            #pragma unroll
            for (int o = 16; o; o >>= 1) psum += __shfl_xor_sync(0xffffffffu, psum, o);
            sRun = sRun * alpha + psum;
            mRun = mNew;
            if (lane < CH) sp[lane * H_NUM + w] = p;
            if (lane == 0) salpha[w] = alpha;
        }
        __syncthreads();

        // ---- aggregation: rescale + accumulate 8 k's, 4 heads per e read ----
        {
            float a0 = salpha[0], a1 = salpha[1], a2 = salpha[2], a3 = salpha[3];
            acc[0].x *= a0; acc[0].y *= a0;
            acc[1].x *= a1; acc[1].y *= a1;
            acc[2].x *= a2; acc[2].y *= a2;
            acc[3].x *= a3; acc[3].y *= a3;
            const float2* E2 = (const float2*)E;
            const float4* sp4 = (const float4*)sp;
            #pragma unroll
            for (int k = 0; k < CH; k++) {
                float4 pv = sp4[k];                  // broadcast
                float2 ev = E2[k * 256 + tid];
                acc[0].x += pv.x * ev.x; acc[0].y += pv.x * ev.y;
                acc[1].x += pv.y * ev.x; acc[1].y += pv.y * ev.y;
                acc[2].x += pv.z * ev.x; acc[2].y += pv.z * ev.y;
                acc[3].x += pv.w * ev.x; acc[3].y += pv.w * ev.y;
            }
        }
        __syncthreads();                             // buffer free

        if (c + 2 < NCH) issue(c + 2, c & 1);
    }

    // ---- finalize: normalize + split-bf16 permuted store ----
    if (w < H_NUM && lane == 0) ssum[w] = sRun;
    __syncthreads();

    const size_t rb = (size_t)r * (H_NUM * D_TOT);
    const int col = tid * 2;
    const int gb = col & ~15;
    const int s0 = slot16(col & 15);
    #pragma unroll
    for (int h = 0; h < H_NUM; h++) {
        float rcp = 1.0f / ssum[h];
        float v0 = acc[h].x * rcp, v1 = acc[h].y * rcp;
        bf16 hh0,hh1,ll0,ll1;
        split1(v0, hh0, ll0);
        split1(v1, hh1, ll1);
        size_t base = rb + (size_t)h * D_TOT + gb + s0;
        *(u32*)(ebh + base) = pkbf(hh0, hh1);
        *(u32*)(ebl + base) = pkbf(ll0, ll1);
    }
}

// ============================================================================
extern "C" void kernel_launch(void* const* d_in, const int* in_sizes, int n_in,
                              void* d_out, int out_size) {
    (void)in_sizes; (void)n_in; (void)out_size;
    const float* e    = (const float*)d_in[0];
    const int*   mask = (const int*)  d_in[1];
    const float* x    = (const float*)d_in[2];
    const float* Wq   = (const float*)d_in[3];
    const float* bq   = (const float*)d_in[4];
    const float* Wk   = (const float*)d_in[5];
    // d_in[6] = bk: softmax-invariant, unused
    const float* Wv   = (const float*)d_in[7];
    const float* bv   = (const float*)d_in[8];
    float* out = (float*)d_out;

    bf16 *xh,*xl,*qh,*ql,*wqh,*wql,*wkh,*wkl,*wvh,*wvl,*ebh,*ebl;
    float *t;
    cudaGetSymbolAddress((void**)&xh,  g_xh);  cudaGetSymbolAddress((void**)&xl,  g_xl);
    cudaGetSymbolAddress((void**)&qh,  g_qh);  cudaGetSymbolAddress((void**)&ql,  g_ql);
    cudaGetSymbolAddress((void**)&wqh, g_wqh); cudaGetSymbolAddress((void**)&wql, g_wql);
    cudaGetSymbolAddress((void**)&wkh, g_wkh); cudaGetSymbolAddress((void**)&wkl, g_wkl);
    cudaGetSymbolAddress((void**)&wvh, g_wvh); cudaGetSymbolAddress((void**)&wvl, g_wvl);
    cudaGetSymbolAddress((void**)&ebh, g_ebh); cudaGetSymbolAddress((void**)&ebl, g_ebl);
    cudaGetSymbolAddress((void**)&t,   g_t);

    // 0) merged prep
    prep_all<<<2816, 256>>>(x, xh, xl, Wq, wqh, wql, Wv, wvh, wvl, Wk, wkh, wkl);

    // 1) q = x @ Wq^T + bq  -> split output
    gemm_bf16x3<true, true><<<dim3(32, 8, 1), 256>>>(
        xh, xl, D_TOT, 0,  wqh, wql, D_TOT, 0,
        nullptr, qh, ql, D_TOT, 0,  bq, 0,  D_TOT);

    // 2) t_h = q_h @ WkT_h^T  (fp32 out)
    gemm_bf16x3<false, false><<<dim3(32, 8, H_NUM), 256>>>(
        qh, ql, D_TOT, DH,  wkh, wkl, DH, D_TOT * DH,
        t, nullptr, nullptr, H_NUM * D_TOT, D_TOT,  nullptr, 0,  DH);

    // 3) flash attention -> eb split
    attn_k<<<R_TOT, 256>>>(e, mask, t, ebh, ebl);

    // 4) out_h = eb_h @ Wv_h^T + bv_h
    gemm_bf16x3<true, false><<<dim3(32, 2, H_NUM), 256>>>(
        ebh, ebl, H_NUM * D_TOT, D_TOT,  wvh, wvl, D_TOT, DH * D_TOT,
        out, nullptr, nullptr, D_TOT, DH,  bv, DH,  D_TOT);
}